// round 2
// baseline (speedup 1.0000x reference)
#include <cuda_runtime.h>
#include <cuda_bf16.h>
#include <mma.h>

using namespace nvcuda;

#define NE 8
#define NTOK 8192
#define DDIM 1024
#define HDIM 2048
#define ODIM 1024
#define OUTC (ODIM + NE)   // 1032

#define BM 128
#define BN 128
#define BK 32
#define NTHREADS 256

#define A_STRIDE (BK + 4)      // 36 floats (144 B, 16B multiple)
#define B_STRIDE (BN + 4)      // 132 floats (528 B, 16B multiple)
#define C_STRIDE (BN + 8)      // 136 floats
#define A_ELEMS  (2 * BM * A_STRIDE)          // 9216 floats
#define B_ELEMS  (2 * BK * B_STRIDE)          // 8448 floats
#define UNION_ELEMS (A_ELEMS + B_ELEMS)       // 17664 floats >= C (128*136=17408)
#define SMEM_FLOATS (UNION_ELEMS + BM)        // + perm[128]
#define SMEM_BYTES (SMEM_FLOATS * 4)          // 71168 B

#define PERM_CAP (NTOK + NE * BM)             // 9216 padded perm slots
#define MAXTILES (PERM_CAP / BM)              // 72

// ---- scratch (__device__ globals; no allocations allowed) ----
__device__ int   g_counts[NE];
__device__ int   g_padoff[NE];
__device__ int   g_padcount[NE];
__device__ int   g_cursor[NE];
__device__ int   g_perm[PERM_CAP];
__device__ float g_hbuf[(size_t)PERM_CAP * HDIM];   // ~75.5 MB intermediate h

// ---------------- cp.async helpers ----------------
__device__ __forceinline__ unsigned smem_u32(const void* p) {
    return (unsigned)__cvta_generic_to_shared(p);
}
__device__ __forceinline__ void cp16(unsigned dst, const void* src) {
    asm volatile("cp.async.cg.shared.global [%0], [%1], 16;\n" :: "r"(dst), "l"(src));
}
#define CP_COMMIT() asm volatile("cp.async.commit_group;\n" ::: "memory")
#define CP_WAIT1()  asm volatile("cp.async.wait_group 1;\n" ::: "memory")
#define CP_WAIT0()  asm volatile("cp.async.wait_group 0;\n" ::: "memory")

// ---------------- routing ----------------
__global__ void k_zero() {
    if (threadIdx.x < NE) g_counts[threadIdx.x] = 0;
}
__global__ void k_init_perm() {
    int i = blockIdx.x * blockDim.x + threadIdx.x;
    if (i < PERM_CAP) g_perm[i] = -1;
}
__global__ void k_count(const int* __restrict__ eidx) {
    int n = blockIdx.x * blockDim.x + threadIdx.x;
    if (n < NTOK) atomicAdd(&g_counts[eidx[n]], 1);
}
__global__ void k_offsets() {
    int acc = 0;
    for (int e = 0; e < NE; e++) {
        int c  = g_counts[e];
        int pc = ((c + BM - 1) / BM) * BM;
        g_padoff[e]   = acc;
        g_cursor[e]   = acc;
        g_padcount[e] = pc;
        acc += pc;
    }
}
__global__ void k_scatter(const int* __restrict__ eidx) {
    int n = blockIdx.x * blockDim.x + threadIdx.x;
    if (n < NTOK) {
        int e = eidx[n];
        int p = atomicAdd(&g_cursor[e], 1);
        g_perm[p] = n;
    }
}

// ---------------- fragment helpers ----------------
using FragA = wmma::fragment<wmma::matrix_a, 16, 16, 8, wmma::precision::tf32, wmma::row_major>;
using FragB = wmma::fragment<wmma::matrix_b, 16, 16, 8, wmma::precision::tf32, wmma::row_major>;
using FragC = wmma::fragment<wmma::accumulator, 16, 16, 8, float>;

__device__ __forceinline__ void cvt_tf32(FragA& f) {
    #pragma unroll
    for (int i = 0; i < f.num_elements; i++) f.x[i] = wmma::__float_to_tf32(f.x[i]);
}
__device__ __forceinline__ void cvt_tf32(FragB& f) {
    #pragma unroll
    for (int i = 0; i < f.num_elements; i++) f.x[i] = wmma::__float_to_tf32(f.x[i]);
}

// ---------------- GEMM1: h[perm-order] = gather(x) @ W1[e] + b1[e] ----------------
// grid: (HDIM/BN, MAXTILES, NE), 256 threads
__global__ void __launch_bounds__(NTHREADS) k_gemm1(const float* __restrict__ x,
                                                    const float* __restrict__ W1,
                                                    const float* __restrict__ b1) {
    int e    = blockIdx.z;
    int rows = g_padcount[e];
    int row0 = blockIdx.y * BM;
    if (row0 >= rows) return;
    int base = g_padoff[e];
    int n0   = blockIdx.x * BN;

    const float* __restrict__ Wb  = W1 + (size_t)e * DDIM * HDIM;
    const float* __restrict__ b1e = b1 + (size_t)e * HDIM;

    extern __shared__ float smem[];
    float* sA = smem;                   // [2][BM][A_STRIDE]
    float* sB = smem + A_ELEMS;         // [2][BK][B_STRIDE]
    float* sC = smem;                   // union reuse
    int*   sperm = (int*)(smem + UNION_ELEMS);

    int tid  = threadIdx.x;
    int warp = tid >> 5;
    int wr   = warp >> 1;   // 0..3 -> 32-row band
    int wc   = warp & 1;    // 0..1 -> 64-col band

    if (tid < BM) {
        int t = g_perm[base + row0 + tid];
        sperm[tid] = (t < 0) ? 0 : t;   // clamp sentinel: compute garbage into padded h row
    }
    __syncthreads();

    FragC acc[2][4];
    #pragma unroll
    for (int i = 0; i < 2; i++)
        #pragma unroll
        for (int j = 0; j < 4; j++)
            wmma::fill_fragment(acc[i][j], 0.0f);

    const int KT = DDIM / BK;   // 32

    // ---- stage loader ----
    auto load_stage = [&](int kt, int buf) {
        int k0 = kt * BK;
        unsigned aB = smem_u32(sA + buf * BM * A_STRIDE);
        unsigned bB = smem_u32(sB + buf * BK * B_STRIDE);
        #pragma unroll
        for (int i = 0; i < 4; i++) {           // A: 128x32 = 1024 float4
            int lin = i * NTHREADS + tid;
            int r   = lin >> 3;
            int c4  = lin & 7;
            int t   = sperm[r];
            cp16(aB + (unsigned)(r * A_STRIDE + c4 * 4) * 4,
                 x + (size_t)t * DDIM + k0 + c4 * 4);
        }
        #pragma unroll
        for (int i = 0; i < 4; i++) {           // B: 32x128 = 1024 float4
            int lin = i * NTHREADS + tid;
            int r   = lin >> 5;
            int c4  = lin & 31;
            cp16(bB + (unsigned)(r * B_STRIDE + c4 * 4) * 4,
                 Wb + (size_t)(k0 + r) * HDIM + n0 + c4 * 4);
        }
        CP_COMMIT();
    };

    load_stage(0, 0);
    for (int kt = 0; kt < KT; kt++) {
        int buf = kt & 1;
        if (kt + 1 < KT) { load_stage(kt + 1, buf ^ 1); CP_WAIT1(); }
        else             { CP_WAIT0(); }
        __syncthreads();

        const float* A0 = sA + buf * BM * A_STRIDE;
        const float* B0 = sB + buf * BK * B_STRIDE;
        #pragma unroll
        for (int kk = 0; kk < BK; kk += 8) {
            FragA a[2];
            FragB b[4];
            wmma::load_matrix_sync(a[0], A0 + (wr * 32 +  0) * A_STRIDE + kk, A_STRIDE);
            wmma::load_matrix_sync(a[1], A0 + (wr * 32 + 16) * A_STRIDE + kk, A_STRIDE);
            cvt_tf32(a[0]); cvt_tf32(a[1]);
            #pragma unroll
            for (int j = 0; j < 4; j++) {
                wmma::load_matrix_sync(b[j], B0 + kk * B_STRIDE + wc * 64 + j * 16, B_STRIDE);
                cvt_tf32(b[j]);
            }
            #pragma unroll
            for (int i = 0; i < 2; i++)
                #pragma unroll
                for (int j = 0; j < 4; j++)
                    wmma::mma_sync(acc[i][j], a[i], b[j], acc[i][j]);
        }
        __syncthreads();
    }

    // ---- epilogue: stage C, add bias, store (full tile; padding rows land in padded hbuf) ----
    #pragma unroll
    for (int i = 0; i < 2; i++)
        #pragma unroll
        for (int j = 0; j < 4; j++)
            wmma::store_matrix_sync(sC + (wr * 32 + i * 16) * C_STRIDE + wc * 64 + j * 16,
                                    acc[i][j], C_STRIDE, wmma::mem_row_major);
    __syncthreads();

    #pragma unroll
    for (int i = 0; i < 16; i++) {              // 128x128 = 4096 float4
        int lin = i * NTHREADS + tid;
        int r   = lin >> 5;
        int c4  = lin & 31;
        float4 v = *reinterpret_cast<const float4*>(sC + r * C_STRIDE + c4 * 4);
        const float4 bb = *reinterpret_cast<const float4*>(&b1e[n0 + c4 * 4]);
        v.x += bb.x; v.y += bb.y; v.z += bb.z; v.w += bb.w;
        *reinterpret_cast<float4*>(&g_hbuf[(size_t)(base + row0 + r) * HDIM + n0 + c4 * 4]) = v;
    }
}

// ---------------- GEMM2: out[perm] = h @ W2[e] + b2[e] ----------------
// grid: (ODIM/BN, MAXTILES, NE), 256 threads
__global__ void __launch_bounds__(NTHREADS) k_gemm2(const float* __restrict__ W2,
                                                    const float* __restrict__ b2,
                                                    float* __restrict__ out) {
    int e    = blockIdx.z;
    int rows = g_padcount[e];
    int row0 = blockIdx.y * BM;
    if (row0 >= rows) return;
    int base = g_padoff[e];
    int n0   = blockIdx.x * BN;

    const float* __restrict__ Wb  = W2 + (size_t)e * HDIM * ODIM;
    const float* __restrict__ b2e = b2 + (size_t)e * ODIM;

    extern __shared__ float smem[];
    float* sA = smem;
    float* sB = smem + A_ELEMS;
    float* sC = smem;
    int*   sperm = (int*)(smem + UNION_ELEMS);

    int tid  = threadIdx.x;
    int warp = tid >> 5;
    int wr   = warp >> 1;
    int wc   = warp & 1;

    if (tid < BM) sperm[tid] = g_perm[base + row0 + tid];  // keep sentinel for scatter mask
    __syncthreads();

    FragC acc[2][4];
    #pragma unroll
    for (int i = 0; i < 2; i++)
        #pragma unroll
        for (int j = 0; j < 4; j++)
            wmma::fill_fragment(acc[i][j], 0.0f);

    const int KT = HDIM / BK;   // 64
    const float* __restrict__ Arows = g_hbuf + (size_t)(base + row0) * HDIM;

    auto load_stage = [&](int kt, int buf) {
        int k0 = kt * BK;
        unsigned aB = smem_u32(sA + buf * BM * A_STRIDE);
        unsigned bB = smem_u32(sB + buf * BK * B_STRIDE);
        #pragma unroll
        for (int i = 0; i < 4; i++) {
            int lin = i * NTHREADS + tid;
            int r   = lin >> 3;
            int c4  = lin & 7;
            cp16(aB + (unsigned)(r * A_STRIDE + c4 * 4) * 4,
                 Arows + (size_t)r * HDIM + k0 + c4 * 4);
        }
        #pragma unroll
        for (int i = 0; i < 4; i++) {
            int lin = i * NTHREADS + tid;
            int r   = lin >> 5;
            int c4  = lin & 31;
            cp16(bB + (unsigned)(r * B_STRIDE + c4 * 4) * 4,
                 Wb + (size_t)(k0 + r) * ODIM + n0 + c4 * 4);
        }
        CP_COMMIT();
    };

    load_stage(0, 0);
    for (int kt = 0; kt < KT; kt++) {
        int buf = kt & 1;
        if (kt + 1 < KT) { load_stage(kt + 1, buf ^ 1); CP_WAIT1(); }
        else             { CP_WAIT0(); }
        __syncthreads();

        const float* A0 = sA + buf * BM * A_STRIDE;
        const float* B0 = sB + buf * BK * B_STRIDE;
        #pragma unroll
        for (int kk = 0; kk < BK; kk += 8) {
            FragA a[2];
            FragB b[4];
            wmma::load_matrix_sync(a[0], A0 + (wr * 32 +  0) * A_STRIDE + kk, A_STRIDE);
            wmma::load_matrix_sync(a[1], A0 + (wr * 32 + 16) * A_STRIDE + kk, A_STRIDE);
            cvt_tf32(a[0]); cvt_tf32(a[1]);
            #pragma unroll
            for (int j = 0; j < 4; j++) {
                wmma::load_matrix_sync(b[j], B0 + kk * B_STRIDE + wc * 64 + j * 16, B_STRIDE);
                cvt_tf32(b[j]);
            }
            #pragma unroll
            for (int i = 0; i < 2; i++)
                #pragma unroll
                for (int j = 0; j < 4; j++)
                    wmma::mma_sync(acc[i][j], a[i], b[j], acc[i][j]);
        }
        __syncthreads();
    }

    #pragma unroll
    for (int i = 0; i < 2; i++)
        #pragma unroll
        for (int j = 0; j < 4; j++)
            wmma::store_matrix_sync(sC + (wr * 32 + i * 16) * C_STRIDE + wc * 64 + j * 16,
                                    acc[i][j], C_STRIDE, wmma::mem_row_major);
    __syncthreads();

    #pragma unroll
    for (int i = 0; i < 16; i++) {
        int lin = i * NTHREADS + tid;
        int r   = lin >> 5;
        int c4  = lin & 31;
        int t   = sperm[r];
        if (t >= 0) {
            float4 v = *reinterpret_cast<const float4*>(sC + r * C_STRIDE + c4 * 4);
            const float4 bb = *reinterpret_cast<const float4*>(&b2e[n0 + c4 * 4]);
            v.x += bb.x; v.y += bb.y; v.z += bb.z; v.w += bb.w;
            *reinterpret_cast<float4*>(&out[(size_t)t * OUTC + n0 + c4 * 4]) = v;
        }
    }
}

// ---------------- onehot tail columns ----------------
__global__ void k_onehot(const int* __restrict__ eidx, float* __restrict__ out) {
    int n = blockIdx.x * blockDim.x + threadIdx.x;
    if (n < NTOK) {
        int e = eidx[n];
        float4 lo = make_float4(e == 0 ? 1.f : 0.f, e == 1 ? 1.f : 0.f,
                                e == 2 ? 1.f : 0.f, e == 3 ? 1.f : 0.f);
        float4 hi = make_float4(e == 4 ? 1.f : 0.f, e == 5 ? 1.f : 0.f,
                                e == 6 ? 1.f : 0.f, e == 7 ? 1.f : 0.f);
        float* row = out + (size_t)n * OUTC + ODIM;
        *reinterpret_cast<float4*>(row)     = lo;
        *reinterpret_cast<float4*>(row + 4) = hi;
    }
}

// ---------------- launch ----------------
extern "C" void kernel_launch(void* const* d_in, const int* in_sizes, int n_in,
                              void* d_out, int out_size) {
    const float* x    = (const float*)d_in[0];
    const float* W1   = (const float*)d_in[1];
    const float* b1   = (const float*)d_in[2];
    const float* W2   = (const float*)d_in[3];
    const float* b2   = (const float*)d_in[4];
    const int*   eidx = (const int*)  d_in[5];
    float* out = (float*)d_out;

    cudaFuncSetAttribute(k_gemm1, cudaFuncAttributeMaxDynamicSharedMemorySize, SMEM_BYTES);
    cudaFuncSetAttribute(k_gemm2, cudaFuncAttributeMaxDynamicSharedMemorySize, SMEM_BYTES);

    k_zero<<<1, 32>>>();
    k_init_perm<<<(PERM_CAP + 255) / 256, 256>>>();
    k_count<<<NTOK / 256, 256>>>(eidx);
    k_offsets<<<1, 1>>>();
    k_scatter<<<NTOK / 256, 256>>>(eidx);

    dim3 g1(HDIM / BN, MAXTILES, NE);   // (16, 72, 8)
    k_gemm1<<<g1, NTHREADS, SMEM_BYTES>>>(x, W1, b1);

    dim3 g2(ODIM / BN, MAXTILES, NE);   // (8, 72, 8)
    k_gemm2<<<g2, NTHREADS, SMEM_BYTES>>>(W2, b2, out);

    k_onehot<<<NTOK / 256, 256>>>(eidx, out);
}

// round 5
// speedup vs baseline: 3.9833x; 3.9833x over previous
#include <cuda_runtime.h>
#include <cuda_fp16.h>
#include <mma.h>
#include <cstdint>

using namespace nvcuda;

#define NE 8
#define NTOK 8192
#define DDIM 1024
#define HDIM 2048
#define ODIM 1024
#define OUTC (ODIM + NE)   // 1032

#define BM 128
#define BN 128
#define BK 32
#define NTHREADS 256
#define NSTAGE 3

// smem strides in HALF elements
#define A_STRIDE 40        // 32 + 8 pad -> 80B rows
#define B_STRIDE 136       // 128 + 8 pad -> 272B rows
#define C_STRIDE 136       // floats
#define A_STAGE_BYTES (BM * A_STRIDE * 2)   // 10240
#define B_STAGE_BYTES (BK * B_STRIDE * 2)   // 8704
#define SMEM_A_OFF 0
#define SMEM_B_OFF (NSTAGE * A_STAGE_BYTES)                 // 30720
#define SMEM_C_BYTES (BM * C_STRIDE * 4)                    // 69632 (union with stages)
#define SMEM_PERM_OFF SMEM_C_BYTES                          // 69632
#define SMEM_BYTES (SMEM_PERM_OFF + BM * 4)                 // 70144

#define PERM_CAP (NTOK + NE * BM)   // 9216
#define MAXTILES (PERM_CAP / BM)    // 72

// ---- scratch (__device__ globals; no allocations allowed) ----
__device__ int    g_counts[NE];
__device__ int    g_padoff[NE];
__device__ int    g_padcount[NE];
__device__ int    g_cursor[NE];
__device__ int    g_perm[PERM_CAP];
__device__ __half g_xh [(size_t)NTOK * DDIM];         // 16 MB
__device__ __half g_w1h[(size_t)NE * DDIM * HDIM];    // 32 MB
__device__ __half g_w2h[(size_t)NE * HDIM * ODIM];    // 32 MB
__device__ __half g_hh [(size_t)PERM_CAP * HDIM];     // 37.7 MB intermediate h (fp16)

// ---- cp.async helpers ----
__device__ __forceinline__ uint32_t smem_u32(const void* p) {
    uint32_t a;
    asm("{ .reg .u64 t; cvta.to.shared.u64 t, %1; cvt.u32.u64 %0, t; }" : "=r"(a) : "l"(p));
    return a;
}
__device__ __forceinline__ void cp16(uint32_t dst, const void* src) {
    asm volatile("cp.async.cg.shared.global [%0], [%1], 16;\n" :: "r"(dst), "l"(src));
}
#define CP_COMMIT() asm volatile("cp.async.commit_group;\n" ::: "memory")
#define CP_WAIT2()  asm volatile("cp.async.wait_group 2;\n" ::: "memory")

// ---------------- routing ----------------
__global__ void k_route_init() {
    int i = blockIdx.x * blockDim.x + threadIdx.x;
    if (i < NE) g_counts[i] = 0;
    if (i < PERM_CAP) g_perm[i] = -1;
}
__global__ void k_count(const int* __restrict__ eidx) {
    int n = blockIdx.x * blockDim.x + threadIdx.x;
    if (n < NTOK) atomicAdd(&g_counts[eidx[n]], 1);
}
__global__ void k_offsets() {
    int acc = 0;
    for (int e = 0; e < NE; e++) {
        int c = g_counts[e];
        int pc = ((c + BM - 1) / BM) * BM;
        g_padoff[e] = acc; g_cursor[e] = acc; g_padcount[e] = pc;
        acc += pc;
    }
}
__global__ void k_scatter(const int* __restrict__ eidx) {
    int n = blockIdx.x * blockDim.x + threadIdx.x;
    if (n < NTOK) g_perm[atomicAdd(&g_cursor[eidx[n]], 1)] = n;
}

// ---------------- fp32 -> fp16 conversions ----------------
// CRITICAL: destination __device__ symbols referenced ONLY in device code.
// (Passing g_xh etc. as a host-side kernel argument takes the host shadow
//  address; on GB300 ATS that write lands in host memory silently.)
__device__ __forceinline__ void cvt_body(const float* __restrict__ src,
                                         __half* __restrict__ dst, size_t n4) {
    size_t i = (size_t)blockIdx.x * blockDim.x + threadIdx.x;
    if (i < n4) {
        float4 v = reinterpret_cast<const float4*>(src)[i];
        __half2 lo = __floats2half2_rn(v.x, v.y);
        __half2 hi = __floats2half2_rn(v.z, v.w);
        reinterpret_cast<__half2*>(dst)[2 * i]     = lo;
        reinterpret_cast<__half2*>(dst)[2 * i + 1] = hi;
    }
}
__global__ void k_cvt_x (const float* __restrict__ s) { cvt_body(s, g_xh,  (size_t)NTOK * DDIM / 4); }
__global__ void k_cvt_w1(const float* __restrict__ s) { cvt_body(s, g_w1h, (size_t)NE * DDIM * HDIM / 4); }
__global__ void k_cvt_w2(const float* __restrict__ s) { cvt_body(s, g_w2h, (size_t)NE * HDIM * ODIM / 4); }

// ---------------- fragments ----------------
using FragA = wmma::fragment<wmma::matrix_a, 16, 16, 16, __half, wmma::row_major>;
using FragB = wmma::fragment<wmma::matrix_b, 16, 16, 16, __half, wmma::row_major>;
using FragC = wmma::fragment<wmma::accumulator, 16, 16, 16, float>;

// ---------------- fp16 grouped GEMM ----------------
// GATHER=1: A = g_xh rows gathered via perm; output -> g_hh (fp16, +bias)
// GATHER=0: A = g_hh contiguous; output -> dst fp32 (+bias), scattered via perm
template<int KDIM, int WLD, bool GATHER, bool SCATTER>
__global__ void __launch_bounds__(NTHREADS, 2) k_gemm(
    const float* __restrict__ bias, float* __restrict__ dst)
{
    int e    = blockIdx.z;
    int rows = g_padcount[e];
    int row0 = blockIdx.y * BM;
    if (row0 >= rows) return;
    int base = g_padoff[e];
    int n0   = blockIdx.x * BN;

    const __half* __restrict__ Asrc = GATHER ? g_xh : g_hh;
    const __half* __restrict__ Wb   = (GATHER ? g_w1h : g_w2h) + (size_t)e * KDIM * WLD;
    const float*  __restrict__ be   = bias + (size_t)e * WLD;

    extern __shared__ char smem[];
    uint32_t smem_base = smem_u32(smem);
    int* sperm = (int*)(smem + SMEM_PERM_OFF);
    float* sC  = (float*)smem;

    int tid  = threadIdx.x;
    int warp = tid >> 5;
    int wr   = warp >> 1;   // 0..3: 32-row band
    int wc   = warp & 1;    // 0..1: 64-col band

    if (tid < BM) sperm[tid] = g_perm[base + row0 + tid];
    __syncthreads();

    FragC acc[2][4];
    #pragma unroll
    for (int i = 0; i < 2; i++)
        #pragma unroll
        for (int j = 0; j < 4; j++)
            wmma::fill_fragment(acc[i][j], 0.0f);

    const int KT = KDIM / BK;

    auto load_stage = [&](int st) {
        if (st < KT) {
            int k0  = st * BK;
            int buf = st % NSTAGE;
            uint32_t aB = smem_base + SMEM_A_OFF + buf * A_STAGE_BYTES;
            uint32_t bB = smem_base + SMEM_B_OFF + buf * B_STAGE_BYTES;
            #pragma unroll
            for (int i = 0; i < 2; i++) {          // A: 128 rows x 32 halves = 512 x 16B
                int lin = i * NTHREADS + tid;
                int r = lin >> 2, c8 = lin & 3;
                const __half* src;
                if (GATHER) {
                    int t = sperm[r]; if (t < 0) t = 0;
                    src = Asrc + (size_t)t * KDIM + k0 + c8 * 8;
                } else {
                    src = Asrc + (size_t)(base + row0 + r) * KDIM + k0 + c8 * 8;
                }
                cp16(aB + r * (A_STRIDE * 2) + c8 * 16, src);
            }
            #pragma unroll
            for (int i = 0; i < 2; i++) {          // B: 32 rows x 128 halves = 512 x 16B
                int lin = i * NTHREADS + tid;
                int r = lin >> 4, c8 = lin & 15;
                cp16(bB + r * (B_STRIDE * 2) + c8 * 16,
                     Wb + (size_t)(k0 + r) * WLD + n0 + c8 * 8);
            }
        }
        CP_COMMIT();
    };

    load_stage(0); load_stage(1); load_stage(2);

    for (int s = 0; s < KT; s++) {
        CP_WAIT2();                  // stage s resident
        __syncthreads();
        int buf = s % NSTAGE;
        const __half* A0 = (const __half*)(smem + SMEM_A_OFF + buf * A_STAGE_BYTES);
        const __half* B0 = (const __half*)(smem + SMEM_B_OFF + buf * B_STAGE_BYTES);
        #pragma unroll
        for (int kk = 0; kk < BK; kk += 16) {
            FragA a[2];
            FragB b[4];
            wmma::load_matrix_sync(a[0], A0 + (wr * 32 +  0) * A_STRIDE + kk, A_STRIDE);
            wmma::load_matrix_sync(a[1], A0 + (wr * 32 + 16) * A_STRIDE + kk, A_STRIDE);
            #pragma unroll
            for (int j = 0; j < 4; j++)
                wmma::load_matrix_sync(b[j], B0 + kk * B_STRIDE + wc * 64 + j * 16, B_STRIDE);
            #pragma unroll
            for (int i = 0; i < 2; i++)
                #pragma unroll
                for (int j = 0; j < 4; j++)
                    wmma::mma_sync(acc[i][j], a[i], b[j], acc[i][j]);
        }
        __syncthreads();             // all warps done with buf before refill
        load_stage(s + NSTAGE);
    }

    // ---- epilogue: stage C in smem (union over stage buffers) ----
    __syncthreads();
    #pragma unroll
    for (int i = 0; i < 2; i++)
        #pragma unroll
        for (int j = 0; j < 4; j++)
            wmma::store_matrix_sync(sC + (wr * 32 + i * 16) * C_STRIDE + wc * 64 + j * 16,
                                    acc[i][j], C_STRIDE, wmma::mem_row_major);
    __syncthreads();

    #pragma unroll
    for (int i = 0; i < 16; i++) {              // 128x128 = 4096 float4 chunks
        int lin = i * NTHREADS + tid;
        int r   = lin >> 5;
        int c4  = lin & 31;
        int t   = sperm[r];
        float4 v = *reinterpret_cast<const float4*>(sC + r * C_STRIDE + c4 * 4);
        const float4 bb = *reinterpret_cast<const float4*>(&be[n0 + c4 * 4]);
        v.x += bb.x; v.y += bb.y; v.z += bb.z; v.w += bb.w;
        if (SCATTER) {
            if (t >= 0) {
                *reinterpret_cast<float4*>(&dst[(size_t)t * OUTC + n0 + c4 * 4]) = v;
            }
        } else {
            // write h as fp16 (padded rows included; harmless garbage)
            __half2 lo = __floats2half2_rn(v.x, v.y);
            __half2 hi = __floats2half2_rn(v.z, v.w);
            uint32_t* p = reinterpret_cast<uint32_t*>(
                g_hh + (size_t)(base + row0 + r) * WLD + n0 + c4 * 4);
            p[0] = *reinterpret_cast<uint32_t*>(&lo);
            p[1] = *reinterpret_cast<uint32_t*>(&hi);
        }
    }
}

// ---------------- onehot tail columns ----------------
__global__ void k_onehot(const int* __restrict__ eidx, float* __restrict__ out) {
    int n = blockIdx.x * blockDim.x + threadIdx.x;
    if (n < NTOK) {
        int e = eidx[n];
        float4 lo = make_float4(e == 0 ? 1.f : 0.f, e == 1 ? 1.f : 0.f,
                                e == 2 ? 1.f : 0.f, e == 3 ? 1.f : 0.f);
        float4 hi = make_float4(e == 4 ? 1.f : 0.f, e == 5 ? 1.f : 0.f,
                                e == 6 ? 1.f : 0.f, e == 7 ? 1.f : 0.f);
        float* row = out + (size_t)n * OUTC + ODIM;
        *reinterpret_cast<float4*>(row)     = lo;
        *reinterpret_cast<float4*>(row + 4) = hi;
    }
}

// ---------------- launch ----------------
extern "C" void kernel_launch(void* const* d_in, const int* in_sizes, int n_in,
                              void* d_out, int out_size) {
    const float* x    = (const float*)d_in[0];
    const float* W1   = (const float*)d_in[1];
    const float* b1   = (const float*)d_in[2];
    const float* W2   = (const float*)d_in[3];
    const float* b2   = (const float*)d_in[4];
    const int*   eidx = (const int*)  d_in[5];
    float* out = (float*)d_out;

    cudaFuncSetAttribute(k_gemm<DDIM, HDIM, true, false>,
                         cudaFuncAttributeMaxDynamicSharedMemorySize, SMEM_BYTES);
    cudaFuncSetAttribute(k_gemm<HDIM, ODIM, false, true>,
                         cudaFuncAttributeMaxDynamicSharedMemorySize, SMEM_BYTES);

    // routing
    k_route_init<<<(PERM_CAP + 255) / 256, 256>>>();
    k_count<<<NTOK / 256, 256>>>(eidx);
    k_offsets<<<1, 1>>>();
    k_scatter<<<NTOK / 256, 256>>>(eidx);

    // fp32 -> fp16 conversions (memory-bound)
    k_cvt_x <<<(NTOK * DDIM / 4 + 255) / 256, 256>>>(x);
    k_cvt_w1<<<(NE * DDIM * HDIM / 4 + 255) / 256, 256>>>(W1);
    k_cvt_w2<<<(NE * HDIM * ODIM / 4 + 255) / 256, 256>>>(W2);

    dim3 g1(HDIM / BN, MAXTILES, NE);   // (16, 72, 8)
    k_gemm<DDIM, HDIM, true, false><<<g1, NTHREADS, SMEM_BYTES>>>(b1, nullptr);

    dim3 g2(ODIM / BN, MAXTILES, NE);   // (8, 72, 8)
    k_gemm<HDIM, ODIM, false, true><<<g2, NTHREADS, SMEM_BYTES>>>(b2, out);

    k_onehot<<<NTOK / 256, 256>>>(eidx, out);
}

// round 6
// speedup vs baseline: 4.0343x; 1.0128x over previous
#include <cuda_runtime.h>
#include <cuda_fp16.h>
#include <mma.h>
#include <cstdint>

using namespace nvcuda;

#define NE 8
#define NTOK 8192
#define DDIM 1024
#define HDIM 2048
#define ODIM 1024
#define OUTC (ODIM + NE)   // 1032

#define BM 128
#define BN 128
#define BK 32
#define NTHREADS 256
#define NSTAGE 4

// smem strides in HALF elements
#define A_STRIDE 40        // 32 + 8 pad -> 80B rows
#define B_STRIDE 136       // 128 + 8 pad -> 272B rows
#define C_STRIDE 136       // floats
#define A_STAGE_BYTES (BM * A_STRIDE * 2)   // 10240
#define B_STAGE_BYTES (BK * B_STRIDE * 2)   // 8704
#define SMEM_A_OFF 0
#define SMEM_B_OFF (NSTAGE * A_STAGE_BYTES)                   // 40960
#define SMEM_STAGE_END (SMEM_B_OFF + NSTAGE * B_STAGE_BYTES)  // 75776
#define SMEM_C_BYTES (BM * C_STRIDE * 4)                      // 69632 (union w/ stages)
#define SMEM_PERM_OFF SMEM_STAGE_END                          // 75776
#define SMEM_BYTES (SMEM_PERM_OFF + BM * 4)                   // 76288

#define PERM_CAP (NTOK + NE * BM)   // 9216
#define MAXTILES (PERM_CAP / BM)    // 72

// ---- scratch (__device__ globals; no allocations allowed) ----
__device__ int    g_padoff[NE];
__device__ int    g_padcount[NE];
__device__ int    g_perm[PERM_CAP];
__device__ __half g_xh [(size_t)NTOK * DDIM];         // 16 MB
__device__ __half g_w1h[(size_t)NE * DDIM * HDIM];    // 32 MB
__device__ __half g_w2h[(size_t)NE * HDIM * ODIM];    // 32 MB
__device__ __half g_hh [(size_t)PERM_CAP * HDIM];     // 37.7 MB intermediate h (fp16)

// ---- cp.async helpers ----
__device__ __forceinline__ uint32_t smem_u32(const void* p) {
    uint32_t a;
    asm("{ .reg .u64 t; cvta.to.shared.u64 t, %1; cvt.u32.u64 %0, t; }" : "=r"(a) : "l"(p));
    return a;
}
__device__ __forceinline__ void cp16(uint32_t dst, const void* src) {
    asm volatile("cp.async.cg.shared.global [%0], [%1], 16;\n" :: "r"(dst), "l"(src));
}
#define CP_COMMIT() asm volatile("cp.async.commit_group;\n" ::: "memory")
#define CP_WAIT2()  asm volatile("cp.async.wait_group 2;\n" ::: "memory")

// ---------------- fused routing + onehot (single block) ----------------
__global__ void __launch_bounds__(1024) k_route(const int* __restrict__ eidx,
                                                float* __restrict__ out) {
    __shared__ int scount[NE];
    __shared__ int soff[NE];
    __shared__ int scursor[NE];
    int tid = threadIdx.x;

    if (tid < NE) scount[tid] = 0;
    __syncthreads();

    // pass 1: counts
    for (int n = tid; n < NTOK; n += 1024) atomicAdd(&scount[eidx[n]], 1);
    __syncthreads();

    if (tid == 0) {
        int acc = 0;
        for (int e = 0; e < NE; e++) {
            int c = scount[e];
            int pc = ((c + BM - 1) / BM) * BM;
            soff[e] = acc; scursor[e] = acc;
            g_padoff[e] = acc; g_padcount[e] = pc;
            acc += pc;
        }
    }
    __syncthreads();

    // sentinel-fill ONLY padding slots [off+count, off+padcount) (disjoint from scatter)
    {
        int e = tid >> 7;          // 8 experts x 128 threads
        int l = tid & 127;
        int c  = scount[e];
        int pc = g_padcount[e];
        for (int i = c + l; i < pc; i += 128) g_perm[soff[e] + i] = -1;
    }

    // pass 2: scatter + onehot tail columns
    for (int n = tid; n < NTOK; n += 1024) {
        int e = eidx[n];
        int p = atomicAdd(&scursor[e], 1);
        g_perm[p] = n;
        float4 lo = make_float4(e == 0 ? 1.f : 0.f, e == 1 ? 1.f : 0.f,
                                e == 2 ? 1.f : 0.f, e == 3 ? 1.f : 0.f);
        float4 hi = make_float4(e == 4 ? 1.f : 0.f, e == 5 ? 1.f : 0.f,
                                e == 6 ? 1.f : 0.f, e == 7 ? 1.f : 0.f);
        float* row = out + (size_t)n * OUTC + ODIM;
        *reinterpret_cast<float4*>(row)     = lo;
        *reinterpret_cast<float4*>(row + 4) = hi;
    }
}

// ---------------- fused fp32 -> fp16 conversion (x, W1, W2 in one launch) ----------------
#define N4_X  ((size_t)NTOK * DDIM / 4)          // 2,097,152
#define N4_W1 ((size_t)NE * DDIM * HDIM / 4)     // 4,194,304
#define N4_W2 ((size_t)NE * HDIM * ODIM / 4)     // 4,194,304
#define N4_TOTAL (N4_X + N4_W1 + N4_W2)

__global__ void k_cvt_all(const float* __restrict__ x,
                          const float* __restrict__ W1,
                          const float* __restrict__ W2) {
    size_t i = (size_t)blockIdx.x * blockDim.x + threadIdx.x;
    if (i >= N4_TOTAL) return;
    const float* src;
    __half* dst;
    size_t j;
    if (i < N4_X)              { src = x;  dst = g_xh;  j = i; }
    else if (i < N4_X + N4_W1) { src = W1; dst = g_w1h; j = i - N4_X; }
    else                       { src = W2; dst = g_w2h; j = i - N4_X - N4_W1; }
    float4 v = reinterpret_cast<const float4*>(src)[j];
    __half2 lo = __floats2half2_rn(v.x, v.y);
    __half2 hi = __floats2half2_rn(v.z, v.w);
    reinterpret_cast<__half2*>(dst)[2 * j]     = lo;
    reinterpret_cast<__half2*>(dst)[2 * j + 1] = hi;
}

// ---------------- fragments ----------------
using FragA = wmma::fragment<wmma::matrix_a, 16, 16, 16, __half, wmma::row_major>;
using FragB = wmma::fragment<wmma::matrix_b, 16, 16, 16, __half, wmma::row_major>;
using FragC = wmma::fragment<wmma::accumulator, 16, 16, 16, float>;

// ---------------- fp16 grouped GEMM (4-stage, one barrier per K-step) ----------------
// GATHER=1: A = g_xh rows gathered via perm; output -> g_hh (fp16, +bias)
// GATHER=0: A = g_hh contiguous; output -> dst fp32 (+bias), scattered via perm
template<int KDIM, int WLD, bool GATHER, bool SCATTER>
__global__ void __launch_bounds__(NTHREADS, 2) k_gemm(
    const float* __restrict__ bias, float* __restrict__ dst)
{
    int e    = blockIdx.z;
    int rows = g_padcount[e];
    int row0 = blockIdx.y * BM;
    if (row0 >= rows) return;
    int base = g_padoff[e];
    int n0   = blockIdx.x * BN;

    const __half* __restrict__ Asrc = GATHER ? g_xh : g_hh;
    const __half* __restrict__ Wb   = (GATHER ? g_w1h : g_w2h) + (size_t)e * KDIM * WLD;
    const float*  __restrict__ be   = bias + (size_t)e * WLD;

    extern __shared__ char smem[];
    uint32_t smem_base = smem_u32(smem);
    int* sperm = (int*)(smem + SMEM_PERM_OFF);
    float* sC  = (float*)smem;

    int tid  = threadIdx.x;
    int warp = tid >> 5;
    int wr   = warp >> 1;   // 0..3: 32-row band
    int wc   = warp & 1;    // 0..1: 64-col band

    if (tid < BM) sperm[tid] = g_perm[base + row0 + tid];
    __syncthreads();

    FragC acc[2][4];
    #pragma unroll
    for (int i = 0; i < 2; i++)
        #pragma unroll
        for (int j = 0; j < 4; j++)
            wmma::fill_fragment(acc[i][j], 0.0f);

    const int KT = KDIM / BK;

    auto load_stage = [&](int st) {
        if (st < KT) {
            int k0  = st * BK;
            int buf = st % NSTAGE;
            uint32_t aB = smem_base + SMEM_A_OFF + buf * A_STAGE_BYTES;
            uint32_t bB = smem_base + SMEM_B_OFF + buf * B_STAGE_BYTES;
            #pragma unroll
            for (int i = 0; i < 2; i++) {          // A: 128 rows x 32 halves = 512 x 16B
                int lin = i * NTHREADS + tid;
                int r = lin >> 2, c8 = lin & 3;
                const __half* src;
                if (GATHER) {
                    int t = sperm[r]; if (t < 0) t = 0;
                    src = Asrc + (size_t)t * KDIM + k0 + c8 * 8;
                } else {
                    src = Asrc + (size_t)(base + row0 + r) * KDIM + k0 + c8 * 8;
                }
                cp16(aB + r * (A_STRIDE * 2) + c8 * 16, src);
            }
            #pragma unroll
            for (int i = 0; i < 2; i++) {          // B: 32 rows x 128 halves = 512 x 16B
                int lin = i * NTHREADS + tid;
                int r = lin >> 4, c8 = lin & 15;
                cp16(bB + r * (B_STRIDE * 2) + c8 * 16,
                     Wb + (size_t)(k0 + r) * WLD + n0 + c8 * 8);
            }
        }
        CP_COMMIT();
    };

    // preload stages 0..2 (3 in flight; 4th buffer free)
    load_stage(0); load_stage(1); load_stage(2);

    for (int s = 0; s < KT; s++) {
        CP_WAIT2();                  // <=2 newer groups pending -> stage s resident (this thread)
        __syncthreads();             // all threads' stage-s copies visible; stage s-1 compute done
        load_stage(s + 3);           // refill buf (s-1)%4 — proven drained by the barrier
        int buf = s % NSTAGE;
        const __half* A0 = (const __half*)(smem + SMEM_A_OFF + buf * A_STAGE_BYTES);
        const __half* B0 = (const __half*)(smem + SMEM_B_OFF + buf * B_STAGE_BYTES);
        #pragma unroll
        for (int kk = 0; kk < BK; kk += 16) {
            FragA a[2];
            FragB b[4];
            wmma::load_matrix_sync(a[0], A0 + (wr * 32 +  0) * A_STRIDE + kk, A_STRIDE);
            wmma::load_matrix_sync(a[1], A0 + (wr * 32 + 16) * A_STRIDE + kk, A_STRIDE);
            #pragma unroll
            for (int j = 0; j < 4; j++)
                wmma::load_matrix_sync(b[j], B0 + kk * B_STRIDE + wc * 64 + j * 16, B_STRIDE);
            #pragma unroll
            for (int i = 0; i < 2; i++)
                #pragma unroll
                for (int j = 0; j < 4; j++)
                    wmma::mma_sync(acc[i][j], a[i], b[j], acc[i][j]);
        }
    }

    // ---- epilogue: stage C in smem (union over stage buffers) ----
    __syncthreads();
    #pragma unroll
    for (int i = 0; i < 2; i++)
        #pragma unroll
        for (int j = 0; j < 4; j++)
            wmma::store_matrix_sync(sC + (wr * 32 + i * 16) * C_STRIDE + wc * 64 + j * 16,
                                    acc[i][j], C_STRIDE, wmma::mem_row_major);
    __syncthreads();

    #pragma unroll
    for (int i = 0; i < 16; i++) {              // 128x128 = 4096 float4 chunks
        int lin = i * NTHREADS + tid;
        int r   = lin >> 5;
        int c4  = lin & 31;
        int t   = sperm[r];
        float4 v = *reinterpret_cast<const float4*>(sC + r * C_STRIDE + c4 * 4);
        const float4 bb = *reinterpret_cast<const float4*>(&be[n0 + c4 * 4]);
        v.x += bb.x; v.y += bb.y; v.z += bb.z; v.w += bb.w;
        if (SCATTER) {
            if (t >= 0) {
                *reinterpret_cast<float4*>(&dst[(size_t)t * OUTC + n0 + c4 * 4]) = v;
            }
        } else {
            __half2 lo = __floats2half2_rn(v.x, v.y);
            __half2 hi = __floats2half2_rn(v.z, v.w);
            uint32_t* p = reinterpret_cast<uint32_t*>(
                g_hh + (size_t)(base + row0 + r) * WLD + n0 + c4 * 4);
            p[0] = *reinterpret_cast<uint32_t*>(&lo);
            p[1] = *reinterpret_cast<uint32_t*>(&hi);
        }
    }
}

// ---------------- launch ----------------
extern "C" void kernel_launch(void* const* d_in, const int* in_sizes, int n_in,
                              void* d_out, int out_size) {
    const float* x    = (const float*)d_in[0];
    const float* W1   = (const float*)d_in[1];
    const float* b1   = (const float*)d_in[2];
    const float* W2   = (const float*)d_in[3];
    const float* b2   = (const float*)d_in[4];
    const int*   eidx = (const int*)  d_in[5];
    float* out = (float*)d_out;

    cudaFuncSetAttribute(k_gemm<DDIM, HDIM, true, false>,
                         cudaFuncAttributeMaxDynamicSharedMemorySize, SMEM_BYTES);
    cudaFuncSetAttribute(k_gemm<HDIM, ODIM, false, true>,
                         cudaFuncAttributeMaxDynamicSharedMemorySize, SMEM_BYTES);

    // routing + onehot (1 block)
    k_route<<<1, 1024>>>(eidx, out);

    // fused fp32->fp16 conversions
    k_cvt_all<<<(int)((N4_TOTAL + 255) / 256), 256>>>(x, W1, W2);

    dim3 g1(HDIM / BN, MAXTILES, NE);   // (16, 72, 8)
    k_gemm<DDIM, HDIM, true, false><<<g1, NTHREADS, SMEM_BYTES>>>(b1, nullptr);

    dim3 g2(ODIM / BN, MAXTILES, NE);   // (8, 72, 8)
    k_gemm<HDIM, ODIM, false, true><<<g2, NTHREADS, SMEM_BYTES>>>(b2, out);
}